// round 11
// baseline (speedup 1.0000x reference)
#include <cuda_runtime.h>
#include <cuda_bf16.h>
#include <math.h>
#include <stdint.h>

static constexpr int kB = 4, kNA = 64, kT = 128, kD = 128, kH = 8, kL = 3;
static constexpr int kDFF = 512, kE = 65536, kNN = kT * kNA, kDH = kD / kH;
static constexpr int kRows = kB * kNA * kT;   // 32768

// ---------------- scratch (device globals; no runtime allocation) ----------
__device__ float g_x  [kRows * kD];
__device__ float g_e  [kRows * kD];
__device__ float g_h1 [kRows * kD];
__device__ float g_pet[kT * kD];
__device__ float g_s   [kB * kNN];
__device__ float g_gout[kB * kNN];
__device__ double g_red[2];

// bf16 hi/lo split activations
__device__ __nv_bfloat16 g_eh [kRows * kD],  g_el [kRows * kD];
__device__ __nv_bfloat16 g_qkvh[kRows * 384], g_qkvl[kRows * 384];
__device__ __nv_bfloat16 g_aoh[kRows * kD],  g_aol[kRows * kD];
__device__ __nv_bfloat16 g_h1h[kRows * kD],  g_h1l[kRows * kD];
__device__ __nv_bfloat16 g_ffh[kRows * kDFF], g_ffl[kRows * kDFF];

// transposed bf16-split weights, per layer block of 196608 elems:
//   [0] QKV^T 384x128 | [49152] O^T 128x128 | [65536] FF1^T 512x128 | [131072] FF2^T 128x512
static constexpr int kWL = 196608;
__device__ __nv_bfloat16 g_wth[kL * kWL];
__device__ __nv_bfloat16 g_wtl[kL * kWL];
__device__ float g_bqkv[kL * 384];

__device__ __forceinline__ void split2(float x, __nv_bfloat16& h, __nv_bfloat16& l) {
    h = __float2bfloat16(x);
    l = __float2bfloat16(x - __bfloat162float(h));
}

// ====================== fused weight conversion ============================
__global__ __launch_bounds__(256) void wconv_all(
        const float* __restrict__ wq, const float* __restrict__ wk,
        const float* __restrict__ wv, const float* __restrict__ wo,
        const float* __restrict__ fw1, const float* __restrict__ fw2) {
    int i = blockIdx.x * blockDim.x + threadIdx.x;
    if (i >= kL * kWL) return;
    int l = i / kWL, off = i - l * kWL;
    const float* W; int N, n, k;
    if (off < 49152) {
        int m = off >> 14, o2 = off & 16383;
        W = (m == 0 ? wq : m == 1 ? wk : wv) + l * 16384;
        n = o2 >> 7; k = o2 & 127; N = 128;
    } else if (off < 65536) {
        int o2 = off - 49152;
        W = wo + l * 16384; n = o2 >> 7; k = o2 & 127; N = 128;
    } else if (off < 131072) {
        int o2 = off - 65536;
        W = fw1 + l * 65536; n = o2 >> 7; k = o2 & 127; N = 512;
    } else {
        int o2 = off - 131072;
        W = fw2 + l * 65536; n = o2 >> 9; k = o2 & 511; N = 128;
    }
    __nv_bfloat16 h, lo;
    split2(W[(size_t)k * N + n], h, lo);
    g_wth[i] = h; g_wtl[i] = lo;
}

__global__ void bqkv_kernel(const float* __restrict__ bq,
                            const float* __restrict__ bk,
                            const float* __restrict__ bv) {
    int i = blockIdx.x * blockDim.x + threadIdx.x;
    if (i >= kL * 384) return;
    int l = i / 384, j = i - l * 384;
    float v = (j < 128) ? bq[l * 128 + j]
            : (j < 256) ? bk[l * 128 + j - 128]
                        : bv[l * 128 + j - 256];
    g_bqkv[i] = v;
}

// positional encoding table (t, d)
__global__ void pet_kernel() {
    int i = blockIdx.x * blockDim.x + threadIdx.x;
    if (i >= kT * kD) return;
    int t = i >> 7, d = i & 127;
    int j = d >> 1;
    float freq = expf(-9.210340371976184f * (float)(2 * j) / (float)kD);
    float ang = (float)t * freq;
    g_pet[i] = (d & 1) ? cosf(ang) : sinf(ang);
}

// ====================== bf16-split MMA GEMM ================================
// K chunk 32, double-buffered (2x40KB = 80KB -> 2 CTA/SM + pipelining).
static constexpr int kPad2 = 80;               // bytes per row (40 bf16)
static constexpr int kArr2 = 128 * kPad2;      // 10240
static constexpr int kBuf2 = 4 * kArr2;        // 40960
static constexpr int kGemmSmem = 2 * kBuf2;    // 81920
static constexpr int kLnStride = 132;          // fits: 128*132*4 = 67584 < 81920

#define LDSM4(r, addr) \
    asm volatile("ldmatrix.sync.aligned.m8n8.x4.shared.b16 {%0,%1,%2,%3}, [%4];" \
        : "=r"((r)[0]), "=r"((r)[1]), "=r"((r)[2]), "=r"((r)[3]) : "r"(addr))
#define LDSM2(r, addr) \
    asm volatile("ldmatrix.sync.aligned.m8n8.x2.shared.b16 {%0,%1}, [%2];" \
        : "=r"((r)[0]), "=r"((r)[1]) : "r"(addr))
#define LDSM2T(r, addr) \
    asm volatile("ldmatrix.sync.aligned.m8n8.x2.trans.shared.b16 {%0,%1}, [%2];" \
        : "=r"((r)[0]), "=r"((r)[1]) : "r"(addr))

__device__ __forceinline__ void mma16816(float* c, const uint32_t* a,
                                         const uint32_t* b) {
    asm volatile(
        "mma.sync.aligned.m16n8k16.row.col.f32.bf16.bf16.f32 "
        "{%0,%1,%2,%3}, {%4,%5,%6,%7}, {%8,%9}, {%0,%1,%2,%3};"
        : "+f"(c[0]), "+f"(c[1]), "+f"(c[2]), "+f"(c[3])
        : "r"(a[0]), "r"(a[1]), "r"(a[2]), "r"(a[3]), "r"(b[0]), "r"(b[1]));
}

// OUT: 0 f32+bias | 1 relu+split | 2 residual+LN | 3 split (no relu)
template <int OUT>
__global__ __launch_bounds__(256) void gemm_mma(
        const __nv_bfloat16* __restrict__ Ahg, const __nv_bfloat16* __restrict__ Alg,
        const __nv_bfloat16* __restrict__ Bhg, const __nv_bfloat16* __restrict__ Blg,
        const float* __restrict__ bias, float* __restrict__ C,
        __nv_bfloat16* __restrict__ Ch, __nv_bfloat16* __restrict__ Cl,
        const float* __restrict__ resid, const float* __restrict__ gamma,
        const float* __restrict__ beta, int N, int K) {
    extern __shared__ char smem[];
    const uint32_t sbase = (uint32_t)__cvta_generic_to_shared(smem);
    const int tid = threadIdx.x;
    const int wid = tid >> 5, lane = tid & 31;
    const int g = lane >> 2, tig = lane & 3;
    const int mw = wid >> 1, nw = wid & 1;
    const int m0 = blockIdx.y * 128, n0 = blockIdx.x * 128;

    float acc[2][8][4];
#pragma unroll
    for (int i = 0; i < 2; i++)
#pragma unroll
        for (int j = 0; j < 8; j++)
#pragma unroll
            for (int t = 0; t < 4; t++) acc[i][j][t] = 0.f;

    const int stages = K >> 5;
    const uint32_t aRowOff = (uint32_t)((lane & 15) * kPad2 + (lane >> 4) * 16);
    const int bRow = (lane & 7) + ((lane >> 4) & 1) * 8;
    const uint32_t bOff = (uint32_t)(bRow * kPad2 + ((lane >> 3) & 1) * 16);

    // cp.async fill: stage s -> buffer b (4 arrays x 128 rows x 64B)
    auto issue = [&](int s, int b) {
#pragma unroll
        for (int it = 0; it < 8; it++) {
            const int arr = it >> 1;
            const int j = tid + ((it & 1) << 8);   // 0..511
            const int r = j >> 2, c = j & 3;
            const __nv_bfloat16* gp;
            if (arr == 0)      gp = Ahg + (size_t)(m0 + r) * K + (s << 5) + c * 8;
            else if (arr == 1) gp = Alg + (size_t)(m0 + r) * K + (s << 5) + c * 8;
            else if (arr == 2) gp = Bhg + (size_t)(n0 + r) * K + (s << 5) + c * 8;
            else               gp = Blg + (size_t)(n0 + r) * K + (s << 5) + c * 8;
            uint32_t dp = sbase + b * kBuf2 + arr * kArr2 + r * kPad2 + c * 16;
            asm volatile("cp.async.ca.shared.global [%0], [%1], 16;"
                         :: "r"(dp), "l"(gp));
        }
        asm volatile("cp.async.commit_group;");
    };

    issue(0, 0);
    for (int s = 0; s < stages; s++) {
        if (s + 1 < stages) {
            issue(s + 1, (s + 1) & 1);
            asm volatile("cp.async.wait_group 1;");
        } else {
            asm volatile("cp.async.wait_group 0;");
        }
        __syncthreads();

        const uint32_t base = sbase + (s & 1) * kBuf2;
        const uint32_t aH = base + (uint32_t)(mw * 32) * kPad2 + aRowOff;
        const uint32_t bH = base + 2 * kArr2 + (uint32_t)(nw * 64) * kPad2 + bOff;
#pragma unroll
        for (int ks = 0; ks < 2; ks++) {
            const uint32_t kb = ks * 32;
            uint32_t ah[2][4], al[2][4];
#pragma unroll
            for (int mt = 0; mt < 2; mt++) {
                LDSM4(ah[mt], aH + mt * (16 * kPad2) + kb);
                LDSM4(al[mt], aH + kArr2 + mt * (16 * kPad2) + kb);
            }
#pragma unroll
            for (int ntp = 0; ntp < 4; ntp++) {
                uint32_t bh[4], bl[4];
                LDSM4(bh, bH + ntp * (16 * kPad2) + kb);
                LDSM4(bl, bH + kArr2 + ntp * (16 * kPad2) + kb);
#pragma unroll
                for (int mt = 0; mt < 2; mt++) {
                    mma16816(acc[mt][2 * ntp], ah[mt], bh);
                    mma16816(acc[mt][2 * ntp], ah[mt], bl);
                    mma16816(acc[mt][2 * ntp], al[mt], bh);
                    mma16816(acc[mt][2 * ntp + 1], ah[mt], bh + 2);
                    mma16816(acc[mt][2 * ntp + 1], ah[mt], bl + 2);
                    mma16816(acc[mt][2 * ntp + 1], al[mt], bh + 2);
                }
            }
        }
        __syncthreads();
    }

    if (OUT == 2) {
        float* Cs = (float*)smem;
#pragma unroll
        for (int mt = 0; mt < 2; mt++) {
#pragma unroll
            for (int nt = 0; nt < 8; nt++) {
                const int col = nw * 64 + nt * 8 + tig * 2;
                const float b0 = bias[col], b1 = bias[col + 1];
                const int r0 = mw * 32 + mt * 16 + g;
                Cs[r0 * kLnStride + col]           = acc[mt][nt][0] + b0;
                Cs[r0 * kLnStride + col + 1]       = acc[mt][nt][1] + b1;
                Cs[(r0 + 8) * kLnStride + col]     = acc[mt][nt][2] + b0;
                Cs[(r0 + 8) * kLnStride + col + 1] = acc[mt][nt][3] + b1;
            }
        }
        __syncthreads();
        const float4 g4 = *(const float4*)&gamma[lane * 4];
        const float4 be4 = *(const float4*)&beta[lane * 4];
#pragma unroll 2
        for (int rr = 0; rr < 16; rr++) {
            const int row = wid * 16 + rr;
            const size_t grow = (size_t)(m0 + row) * 128 + lane * 4;
            float4 v = *(float4*)&Cs[row * kLnStride + lane * 4];
            const float4 rs4 = *(const float4*)&resid[grow];
            v.x += rs4.x; v.y += rs4.y; v.z += rs4.z; v.w += rs4.w;
            float s = v.x + v.y + v.z + v.w;
#pragma unroll
            for (int o = 16; o > 0; o >>= 1) s += __shfl_xor_sync(~0u, s, o);
            const float mean = s * (1.f / 128.f);
            float dx = v.x - mean, dy = v.y - mean, dz = v.z - mean,
                  dw = v.w - mean;
            float ss = dx * dx + dy * dy + dz * dz + dw * dw;
#pragma unroll
            for (int o = 16; o > 0; o >>= 1) ss += __shfl_xor_sync(~0u, ss, o);
            const float rstd = rsqrtf(ss * (1.f / 128.f) + 1e-5f);
            float4 ov;
            ov.x = dx * rstd * g4.x + be4.x;
            ov.y = dy * rstd * g4.y + be4.y;
            ov.z = dz * rstd * g4.z + be4.z;
            ov.w = dw * rstd * g4.w + be4.w;
            *(float4*)&C[grow] = ov;
            __nv_bfloat162 h0, l0, h1, l1;
            split2(ov.x, h0.x, l0.x); split2(ov.y, h0.y, l0.y);
            split2(ov.z, h1.x, l1.x); split2(ov.w, h1.y, l1.y);
            *(__nv_bfloat162*)&Ch[grow] = h0;
            *(__nv_bfloat162*)&Ch[grow + 2] = h1;
            *(__nv_bfloat162*)&Cl[grow] = l0;
            *(__nv_bfloat162*)&Cl[grow + 2] = l1;
        }
        return;
    }

#pragma unroll
    for (int mt = 0; mt < 2; mt++) {
#pragma unroll
        for (int nt = 0; nt < 8; nt++) {
            const int col = n0 + nw * 64 + nt * 8 + tig * 2;
            const float b0 = bias[col], b1 = bias[col + 1];
            const int r0 = m0 + mw * 32 + mt * 16 + g;
            float v00 = acc[mt][nt][0] + b0, v01 = acc[mt][nt][1] + b1;
            float v10 = acc[mt][nt][2] + b0, v11 = acc[mt][nt][3] + b1;
            if (OUT == 1 || OUT == 3) {
                if (OUT == 1) {
                    v00 = fmaxf(v00, 0.f); v01 = fmaxf(v01, 0.f);
                    v10 = fmaxf(v10, 0.f); v11 = fmaxf(v11, 0.f);
                }
                __nv_bfloat162 h0, l0, h1, l1;
                split2(v00, h0.x, l0.x); split2(v01, h0.y, l0.y);
                split2(v10, h1.x, l1.x); split2(v11, h1.y, l1.y);
                *(__nv_bfloat162*)&Ch[(size_t)r0 * N + col] = h0;
                *(__nv_bfloat162*)&Cl[(size_t)r0 * N + col] = l0;
                *(__nv_bfloat162*)&Ch[(size_t)(r0 + 8) * N + col] = h1;
                *(__nv_bfloat162*)&Cl[(size_t)(r0 + 8) * N + col] = l1;
            } else {
                *(float2*)&C[(size_t)r0 * N + col] = {v00, v01};
                *(float2*)&C[(size_t)(r0 + 8) * N + col] = {v10, v11};
            }
        }
    }
}

// ---------------- zero accumulators --------------------------------------
__global__ void zero_kernel() {
    int i = blockIdx.x * blockDim.x + threadIdx.x;
    if (i < kB * kNN) g_gout[i] = 0.f;
    if (i < 2) g_red[i] = 0.0;
}

// ---------------- hist projection + positional encoding -------------------
__global__ __launch_bounds__(256) void hist_pe_kernel(
        const float* __restrict__ feat, const float* __restrict__ w,
        const float* __restrict__ bias) {
    int idx = blockIdx.x * 256 + threadIdx.x;
    int row = idx >> 7, d = idx & 127;
    float f0 = feat[row * 3 + 0], f1 = feat[row * 3 + 1], f2 = feat[row * 3 + 2];
    float x = f0 * w[d] + f1 * w[kD + d] + f2 * w[2 * kD + d] + bias[d];
    g_x[idx] = x;
    int t = row & (kT - 1);
    float e = x + g_pet[t * kD + d];
    g_e[idx] = e;
    __nv_bfloat16 h, l;
    split2(e, h, l);
    g_eh[idx] = h;
    g_el[idx] = l;
}

// ---------------- tensor-core attention: 1 warp per (bn, head) -------------
static constexpr int kAStr = 24;   // bf16 elems per smem row (48B, aligned)

__global__ __launch_bounds__(64) void attn_mma_kernel() {
    const int bn = blockIdx.x;
    const int w = threadIdx.x >> 5, lane = threadIdx.x & 31;
    const int h = blockIdx.y * 2 + w;
    const int g = lane >> 2, tig = lane & 3;
    __shared__ __nv_bfloat16 sKV[2][4][128 * kAStr];  // [warp][Kh,Kl,Vh,Vl]

    {
        const int colK = 128 + h * 16, colV = 256 + h * 16;
#pragma unroll
        for (int a = 0; a < 4; a++) {
            const __nv_bfloat16* src = (a & 1) ? g_qkvl : g_qkvh;
            const int col = (a < 2) ? colK : colV;
            __nv_bfloat16* dst = sKV[w][a];
#pragma unroll
            for (int i = lane; i < 256; i += 32) {
                int row = i >> 1, half = i & 1;
                *(uint4*)&dst[row * kAStr + half * 8] =
                    *(const uint4*)&src[(size_t)(bn * 128 + row) * 384 + col + half * 8];
            }
        }
    }
    __syncwarp();

    uint32_t kvb[4];
#pragma unroll
    for (int a = 0; a < 4; a++)
        kvb[a] = (uint32_t)__cvta_generic_to_shared(&sKV[w][a][0]);

    const uint32_t offK = (uint32_t)((lane & 7) * 48 + ((lane >> 3) & 1) * 16);
    const uint32_t offV = (uint32_t)(((lane & 7) + ((lane >> 3) & 1) * 8) * 48);

    for (int mt = 0; mt < 8; mt++) {
        const size_t r0 = (size_t)(bn * 128 + mt * 16 + g) * 384 + h * 16 + tig * 2;
        const size_t r1 = r0 + 8 * 384;
        uint32_t qh[4], ql[4];
        qh[0] = *(const uint32_t*)&g_qkvh[r0];
        qh[1] = *(const uint32_t*)&g_qkvh[r1];
        qh[2] = *(const uint32_t*)&g_qkvh[r0 + 8];
        qh[3] = *(const uint32_t*)&g_qkvh[r1 + 8];
        ql[0] = *(const uint32_t*)&g_qkvl[r0];
        ql[1] = *(const uint32_t*)&g_qkvl[r1];
        ql[2] = *(const uint32_t*)&g_qkvl[r0 + 8];
        ql[3] = *(const uint32_t*)&g_qkvl[r1 + 8];

        float c[16][4];
#pragma unroll
        for (int j = 0; j < 16; j++)
#pragma unroll
            for (int t = 0; t < 4; t++) c[j][t] = 0.f;

#pragma unroll
        for (int j = 0; j < 16; j++) {
            uint32_t kh[2], kl[2];
            LDSM2(kh, kvb[0] + j * 384 + offK);
            LDSM2(kl, kvb[1] + j * 384 + offK);
            mma16816(c[j], qh, kh);
            mma16816(c[j], qh, kl);
            mma16816(c[j], ql, kh);
        }

        float mx0 = -1e30f, mx1 = -1e30f;
#pragma unroll
        for (int j = 0; j < 16; j++) {
            c[j][0] *= 0.25f; c[j][1] *= 0.25f;
            c[j][2] *= 0.25f; c[j][3] *= 0.25f;
            mx0 = fmaxf(mx0, fmaxf(c[j][0], c[j][1]));
            mx1 = fmaxf(mx1, fmaxf(c[j][2], c[j][3]));
        }
        mx0 = fmaxf(mx0, __shfl_xor_sync(~0u, mx0, 1));
        mx0 = fmaxf(mx0, __shfl_xor_sync(~0u, mx0, 2));
        mx1 = fmaxf(mx1, __shfl_xor_sync(~0u, mx1, 1));
        mx1 = fmaxf(mx1, __shfl_xor_sync(~0u, mx1, 2));
        float sm0 = 0.f, sm1 = 0.f;
#pragma unroll
        for (int j = 0; j < 16; j++) {
            c[j][0] = __expf(c[j][0] - mx0); sm0 += c[j][0];
            c[j][1] = __expf(c[j][1] - mx0); sm0 += c[j][1];
            c[j][2] = __expf(c[j][2] - mx1); sm1 += c[j][2];
            c[j][3] = __expf(c[j][3] - mx1); sm1 += c[j][3];
        }
        sm0 += __shfl_xor_sync(~0u, sm0, 1);
        sm0 += __shfl_xor_sync(~0u, sm0, 2);
        sm1 += __shfl_xor_sync(~0u, sm1, 1);
        sm1 += __shfl_xor_sync(~0u, sm1, 2);

        float o[2][4];
#pragma unroll
        for (int n = 0; n < 2; n++)
#pragma unroll
            for (int t = 0; t < 4; t++) o[n][t] = 0.f;

#pragma unroll
        for (int ks = 0; ks < 8; ks++) {
            uint32_t ph[4], pl[4];
#pragma unroll
            for (int half = 0; half < 2; half++) {
                const float* cv = c[2 * ks + half];
                __nv_bfloat162 h01, l01, h23, l23;
                split2(cv[0], h01.x, l01.x); split2(cv[1], h01.y, l01.y);
                split2(cv[2], h23.x, l23.x); split2(cv[3], h23.y, l23.y);
                ph[half * 2 + 0] = *(uint32_t*)&h01;
                ph[half * 2 + 1] = *(uint32_t*)&h23;
                pl[half * 2 + 0] = *(uint32_t*)&l01;
                pl[half * 2 + 1] = *(uint32_t*)&l23;
            }
            uint32_t pha[4] = {ph[0], ph[1], ph[2], ph[3]};
            uint32_t pla[4] = {pl[0], pl[1], pl[2], pl[3]};
#pragma unroll
            for (int n = 0; n < 2; n++) {
                uint32_t vh[2], vl[2];
                LDSM2T(vh, kvb[2] + ks * 768 + offV + n * 16);
                LDSM2T(vl, kvb[3] + ks * 768 + offV + n * 16);
                mma16816(o[n], pha, vh);
                mma16816(o[n], pha, vl);
                mma16816(o[n], pla, vh);
            }
        }

        const float i0 = 1.f / sm0, i1 = 1.f / sm1;
        const size_t ro = (size_t)(bn * 128 + mt * 16 + g) * 128 + h * 16;
#pragma unroll
        for (int n = 0; n < 2; n++) {
            const size_t cA = ro + n * 8 + tig * 2;
            const size_t cB = cA + 8 * 128;
            __nv_bfloat162 h0, l0, h1, l1;
            split2(o[n][0] * i0, h0.x, l0.x);
            split2(o[n][1] * i0, h0.y, l0.y);
            split2(o[n][2] * i1, h1.x, l1.x);
            split2(o[n][3] * i1, h1.y, l1.y);
            *(__nv_bfloat162*)&g_aoh[cA] = h0;
            *(__nv_bfloat162*)&g_aol[cA] = l0;
            *(__nv_bfloat162*)&g_aoh[cB] = h1;
            *(__nv_bfloat162*)&g_aol[cB] = l1;
        }
    }
}

// ---------------- node score ----------------------------------------------
__global__ __launch_bounds__(128) void s_kernel() {
    int row = blockIdx.x, t = threadIdx.x;
    float p = g_e[row * kD + t] * g_x[row * kD + t];
    __shared__ float ws[4];
#pragma unroll
    for (int o = 16; o > 0; o >>= 1) p += __shfl_xor_sync(~0u, p, o);
    if ((t & 31) == 0) ws[t >> 5] = p;
    __syncthreads();
    if (t == 0) {
        float tot = ws[0] + ws[1] + ws[2] + ws[3];
        int b = row / (kNA * kT);
        int rem = row % (kNA * kT);
        int n = rem / kT, tt = rem % kT;
        g_s[b * kNN + tt * kNA + n] = tot;
    }
}

// ---------------- edge segment-sum ----------------------------------------
__global__ void edge_kernel(const int* __restrict__ ei,
                            const float* __restrict__ ew) {
    int idx = blockIdx.x * blockDim.x + threadIdx.x;
    if (idx >= kB * kE) return;
    int b = idx / kE, e = idx - b * kE;
    int src = ei[b * 2 * kE + e];
    int dst = ei[b * 2 * kE + kE + e];
    atomicAdd(&g_gout[b * kNN + dst], ew[idx] * g_s[b * kNN + src]);
}

// ---------------- global mean/var over gout -------------------------------
__global__ __launch_bounds__(256) void stats_kernel() {
    int i = blockIdx.x * blockDim.x + threadIdx.x;
    double s = 0.0, s2 = 0.0;
    for (int k = i; k < kB * kNN; k += gridDim.x * blockDim.x) {
        double v = (double)g_gout[k];
        s += v; s2 += v * v;
    }
#pragma unroll
    for (int o = 16; o > 0; o >>= 1) {
        s  += __shfl_xor_sync(~0u, s, o);
        s2 += __shfl_xor_sync(~0u, s2, o);
    }
    __shared__ double ws[8][2];
    int w = threadIdx.x >> 5;
    if ((threadIdx.x & 31) == 0) { ws[w][0] = s; ws[w][1] = s2; }
    __syncthreads();
    if (threadIdx.x == 0) {
        double a = 0, b2 = 0;
        for (int k = 0; k < 8; k++) { a += ws[k][0]; b2 += ws[k][1]; }
        atomicAdd(&g_red[0], a);
        atomicAdd(&g_red[1], b2);
    }
}

// ---------------- batchnorm + rank-1 output --------------------------------
__global__ void out_kernel(const float* __restrict__ bng,
                           const float* __restrict__ bnb,
                           const float* __restrict__ lw,
                           const float* __restrict__ lb,
                           float* __restrict__ out) {
    int idx = blockIdx.x * blockDim.x + threadIdx.x;
    if (idx >= kRows * kD) return;
    int d = idx & 127;
    int t = (idx >> 7) & 127;
    int n = (idx >> 14) & 63;
    int b = idx >> 20;
    const double inv_n = 1.0 / (double)(kB * kNN);
    double m = g_red[0] * inv_n;
    double var = g_red[1] * inv_n - m * m;
    double rs = 1.0 / sqrt(var + 1e-5);
    float gv = g_gout[b * kNN + t * kNA + n];
    float norm = (float)(((double)gv - m) * rs) * bng[0] + bnb[0];
    out[idx] = norm * lw[d] + lb[d];
}

// ---------------- launch ---------------------------------------------------
extern "C" void kernel_launch(void* const* d_in, const int* in_sizes, int n_in,
                              void* d_out, int out_size) {
    const float* feat  = (const float*)d_in[0];
    const int*   eidx  = (const int*)d_in[1];
    const float* ew    = (const float*)d_in[2];
    const float* histw = (const float*)d_in[3];
    const float* histb = (const float*)d_in[4];
    const float* wq    = (const float*)d_in[5];
    const float* bq    = (const float*)d_in[6];
    const float* wk    = (const float*)d_in[7];
    const float* bk    = (const float*)d_in[8];
    const float* wv    = (const float*)d_in[9];
    const float* bv    = (const float*)d_in[10];
    const float* wo    = (const float*)d_in[11];
    const float* bo    = (const float*)d_in[12];
    const float* ln1g  = (const float*)d_in[13];
    const float* ln1b  = (const float*)d_in[14];
    const float* fw1   = (const float*)d_in[15];
    const float* fb1   = (const float*)d_in[16];
    const float* fw2   = (const float*)d_in[17];
    const float* fb2   = (const float*)d_in[18];
    const float* ln2g  = (const float*)d_in[19];
    const float* ln2b  = (const float*)d_in[20];
    const float* bng   = (const float*)d_in[21];
    const float* bnb   = (const float*)d_in[22];
    const float* lgw   = (const float*)d_in[23];
    const float* lgb   = (const float*)d_in[24];
    float* out = (float*)d_out;

    float *pe, *ph1, *pbqkv;
    __nv_bfloat16 *pwh, *pwl, *peh, *pel, *paoh, *paol, *ph1h, *ph1l, *pffh, *pffl,
                  *pqkvh, *pqkvl;
    cudaGetSymbolAddress((void**)&pe,   g_e);
    cudaGetSymbolAddress((void**)&ph1,  g_h1);
    cudaGetSymbolAddress((void**)&pwh,  g_wth);
    cudaGetSymbolAddress((void**)&pwl,  g_wtl);
    cudaGetSymbolAddress((void**)&pbqkv, g_bqkv);
    cudaGetSymbolAddress((void**)&peh,  g_eh);
    cudaGetSymbolAddress((void**)&pel,  g_el);
    cudaGetSymbolAddress((void**)&paoh, g_aoh);
    cudaGetSymbolAddress((void**)&paol, g_aol);
    cudaGetSymbolAddress((void**)&ph1h, g_h1h);
    cudaGetSymbolAddress((void**)&ph1l, g_h1l);
    cudaGetSymbolAddress((void**)&pffh, g_ffh);
    cudaGetSymbolAddress((void**)&pffl, g_ffl);
    cudaGetSymbolAddress((void**)&pqkvh, g_qkvh);
    cudaGetSymbolAddress((void**)&pqkvl, g_qkvl);

    cudaFuncSetAttribute(gemm_mma<0>,
                         cudaFuncAttributeMaxDynamicSharedMemorySize, kGemmSmem);
    cudaFuncSetAttribute(gemm_mma<1>,
                         cudaFuncAttributeMaxDynamicSharedMemorySize, kGemmSmem);
    cudaFuncSetAttribute(gemm_mma<2>,
                         cudaFuncAttributeMaxDynamicSharedMemorySize, kGemmSmem);
    cudaFuncSetAttribute(gemm_mma<3>,
                         cudaFuncAttributeMaxDynamicSharedMemorySize, kGemmSmem);

    zero_kernel<<<(kB * kNN + 255) / 256, 256>>>();
    pet_kernel<<<(kT * kD + 255) / 256, 256>>>();
    bqkv_kernel<<<(kL * 384 + 255) / 256, 256>>>(bq, bk, bv);
    wconv_all<<<(kL * kWL + 255) / 256, 256>>>(wq, wk, wv, wo, fw1, fw2);
    hist_pe_kernel<<<kRows * kD / 256, 256>>>(feat, histw, histb);

    const int MT = kRows / 128;  // 256 M tiles
    for (int l = 0; l < kL; l++) {
        const int base = l * kWL;
        // QKV fused: N=384, K=128 -> bf16 splits
        gemm_mma<3><<<dim3(3, MT), 256, kGemmSmem>>>(
            peh, pel, pwh + base, pwl + base, pbqkv + l * 384,
            nullptr, pqkvh, pqkvl, nullptr, nullptr, nullptr, 384, 128);
        attn_mma_kernel<<<dim3(kB * kNA, kH / 2), 64>>>();
        // O proj + residual(e) + LN1 -> h1 (f32 + splits)
        gemm_mma<2><<<dim3(1, MT), 256, kGemmSmem>>>(
            paoh, paol, pwh + base + 49152, pwl + base + 49152, bo + l * kD,
            ph1, ph1h, ph1l, pe, ln1g + l * kD, ln1b + l * kD, 128, 128);
        // FF1: N=512, K=128, relu + split out
        gemm_mma<1><<<dim3(4, MT), 256, kGemmSmem>>>(
            ph1h, ph1l, pwh + base + 65536, pwl + base + 65536, fb1 + l * kDFF,
            nullptr, pffh, pffl, nullptr, nullptr, nullptr, 512, 128);
        // FF2 + residual(h1) + LN2 -> e (f32 + splits)
        gemm_mma<2><<<dim3(1, MT), 256, kGemmSmem>>>(
            pffh, pffl, pwh + base + 131072, pwl + base + 131072, fb2 + l * kD,
            pe, peh, pel, ph1, ln2g + l * kD, ln2b + l * kD, 128, 512);
    }

    s_kernel<<<kRows, 128>>>();
    edge_kernel<<<(kB * kE + 255) / 256, 256>>>(eidx, ew);
    stats_kernel<<<64, 256>>>();
    out_kernel<<<(kRows * kD + 255) / 256, 256>>>(bng, bnb, lgw, lgb, out);
}

// round 12
// speedup vs baseline: 1.0266x; 1.0266x over previous
#include <cuda_runtime.h>
#include <cuda_bf16.h>
#include <math.h>
#include <stdint.h>

static constexpr int kB = 4, kNA = 64, kT = 128, kD = 128, kH = 8, kL = 3;
static constexpr int kDFF = 512, kE = 65536, kNN = kT * kNA, kDH = kD / kH;
static constexpr int kRows = kB * kNA * kT;   // 32768

// ---------------- scratch (device globals; no runtime allocation) ----------
__device__ float g_x  [kRows * kD];
__device__ float g_e  [kRows * kD];
__device__ float g_h1 [kRows * kD];
__device__ float g_pet[kT * kD];
__device__ float g_s   [kB * kNN];
__device__ float g_gout[kB * kNN];
__device__ double g_red[2];

// bf16 hi/lo split activations
__device__ __nv_bfloat16 g_eh [kRows * kD],  g_el [kRows * kD];
__device__ __nv_bfloat16 g_qkvh[kRows * 384], g_qkvl[kRows * 384];
__device__ __nv_bfloat16 g_aoh[kRows * kD],  g_aol[kRows * kD];
__device__ __nv_bfloat16 g_h1h[kRows * kD],  g_h1l[kRows * kD];
__device__ __nv_bfloat16 g_ffh[kRows * kDFF], g_ffl[kRows * kDFF];

// transposed bf16-split weights, per layer block of 196608 elems:
//   [0] QKV^T 384x128 | [49152] O^T 128x128 | [65536] FF1^T 512x128 | [131072] FF2^T 128x512
static constexpr int kWL = 196608;
__device__ __nv_bfloat16 g_wth[kL * kWL];
__device__ __nv_bfloat16 g_wtl[kL * kWL];
__device__ float g_bqkv[kL * 384];

__device__ __forceinline__ void split2(float x, __nv_bfloat16& h, __nv_bfloat16& l) {
    h = __float2bfloat16(x);
    l = __float2bfloat16(x - __bfloat162float(h));
}

// ====================== fused setup: zero + PE table + qkv bias ============
__global__ __launch_bounds__(256) void setup_kernel(
        const float* __restrict__ bq, const float* __restrict__ bk,
        const float* __restrict__ bv) {
    int i = blockIdx.x * 256 + threadIdx.x;
    if (i < kB * kNN) g_gout[i] = 0.f;
    if (i < 2) g_red[i] = 0.0;
    if (i < kT * kD) {
        int t = i >> 7, d = i & 127;
        int j = d >> 1;
        float freq = expf(-9.210340371976184f * (float)(2 * j) / (float)kD);
        float ang = (float)t * freq;
        g_pet[i] = (d & 1) ? cosf(ang) : sinf(ang);
    }
    if (i < kL * 384) {
        int l = i / 384, j = i - l * 384;
        float v = (j < 128) ? bq[l * 128 + j]
                : (j < 256) ? bk[l * 128 + j - 128]
                            : bv[l * 128 + j - 256];
        g_bqkv[i] = v;
    }
}

// ====================== fused weight conversion ============================
__global__ __launch_bounds__(256) void wconv_all(
        const float* __restrict__ wq, const float* __restrict__ wk,
        const float* __restrict__ wv, const float* __restrict__ wo,
        const float* __restrict__ fw1, const float* __restrict__ fw2) {
    int i = blockIdx.x * blockDim.x + threadIdx.x;
    if (i >= kL * kWL) return;
    int l = i / kWL, off = i - l * kWL;
    const float* W; int N, n, k;
    if (off < 49152) {
        int m = off >> 14, o2 = off & 16383;
        W = (m == 0 ? wq : m == 1 ? wk : wv) + l * 16384;
        n = o2 >> 7; k = o2 & 127; N = 128;
    } else if (off < 65536) {
        int o2 = off - 49152;
        W = wo + l * 16384; n = o2 >> 7; k = o2 & 127; N = 128;
    } else if (off < 131072) {
        int o2 = off - 65536;
        W = fw1 + l * 65536; n = o2 >> 7; k = o2 & 127; N = 512;
    } else {
        int o2 = off - 131072;
        W = fw2 + l * 65536; n = o2 >> 9; k = o2 & 511; N = 128;
    }
    __nv_bfloat16 h, lo;
    split2(W[(size_t)k * N + n], h, lo);
    g_wth[i] = h; g_wtl[i] = lo;
}

// ====================== bf16-split MMA GEMM ================================
// Single buffer, K chunk 64 (73.7KB -> 2 CTA/SM). Proven best config.
static constexpr int kPadB = 144;
static constexpr int kArrB = 128 * kPadB;      // 18432
static constexpr int kBufB = 4 * kArrB;        // 73728
static constexpr int kGemmSmem = kBufB;
static constexpr int kLnStride = 132;

#define LDSM4(r, addr) \
    asm volatile("ldmatrix.sync.aligned.m8n8.x4.shared.b16 {%0,%1,%2,%3}, [%4];" \
        : "=r"((r)[0]), "=r"((r)[1]), "=r"((r)[2]), "=r"((r)[3]) : "r"(addr))
#define LDSM2(r, addr) \
    asm volatile("ldmatrix.sync.aligned.m8n8.x2.shared.b16 {%0,%1}, [%2];" \
        : "=r"((r)[0]), "=r"((r)[1]) : "r"(addr))
#define LDSM2T(r, addr) \
    asm volatile("ldmatrix.sync.aligned.m8n8.x2.trans.shared.b16 {%0,%1}, [%2];" \
        : "=r"((r)[0]), "=r"((r)[1]) : "r"(addr))

__device__ __forceinline__ void mma16816(float* c, const uint32_t* a,
                                         const uint32_t* b) {
    asm volatile(
        "mma.sync.aligned.m16n8k16.row.col.f32.bf16.bf16.f32 "
        "{%0,%1,%2,%3}, {%4,%5,%6,%7}, {%8,%9}, {%0,%1,%2,%3};"
        : "+f"(c[0]), "+f"(c[1]), "+f"(c[2]), "+f"(c[3])
        : "r"(a[0]), "r"(a[1]), "r"(a[2]), "r"(a[3]), "r"(b[0]), "r"(b[1]));
}

// OUT: 0 f32+bias | 1 relu+split | 2 residual+LN | 3 split (no relu)
template <int OUT>
__global__ __launch_bounds__(256) void gemm_mma(
        const __nv_bfloat16* __restrict__ Ahg, const __nv_bfloat16* __restrict__ Alg,
        const __nv_bfloat16* __restrict__ Bhg, const __nv_bfloat16* __restrict__ Blg,
        const float* __restrict__ bias, float* __restrict__ C,
        __nv_bfloat16* __restrict__ Ch, __nv_bfloat16* __restrict__ Cl,
        const float* __restrict__ resid, const float* __restrict__ gamma,
        const float* __restrict__ beta, int N, int K) {
    extern __shared__ char smem[];
    const uint32_t sbase = (uint32_t)__cvta_generic_to_shared(smem);
    const int tid = threadIdx.x;
    const int wid = tid >> 5, lane = tid & 31;
    const int g = lane >> 2, tig = lane & 3;
    const int mw = wid >> 1, nw = wid & 1;
    const int m0 = blockIdx.y * 128, n0 = blockIdx.x * 128;

    float acc[2][8][4];
#pragma unroll
    for (int i = 0; i < 2; i++)
#pragma unroll
        for (int j = 0; j < 8; j++)
#pragma unroll
            for (int t = 0; t < 4; t++) acc[i][j][t] = 0.f;

    const int stages = K >> 6;
    const uint32_t aRowOff = (uint32_t)((lane & 15) * kPadB + (lane >> 4) * 16);
    const int bRow = (lane & 7) + ((lane >> 4) & 1) * 8;
    const uint32_t bOff = (uint32_t)(bRow * kPadB + ((lane >> 3) & 1) * 16);

    for (int s = 0; s < stages; s++) {
#pragma unroll
        for (int it = 0; it < 16; it++) {
            const int arr = it >> 2;
            const int j = tid + ((it & 3) << 8);
            const int r = j >> 3, c = j & 7;
            const __nv_bfloat16* gp;
            if (arr == 0)      gp = Ahg + (size_t)(m0 + r) * K + (s << 6) + c * 8;
            else if (arr == 1) gp = Alg + (size_t)(m0 + r) * K + (s << 6) + c * 8;
            else if (arr == 2) gp = Bhg + (size_t)(n0 + r) * K + (s << 6) + c * 8;
            else               gp = Blg + (size_t)(n0 + r) * K + (s << 6) + c * 8;
            uint32_t dp = sbase + arr * kArrB + r * kPadB + c * 16;
            asm volatile("cp.async.ca.shared.global [%0], [%1], 16;"
                         :: "r"(dp), "l"(gp));
        }
        asm volatile("cp.async.commit_group;");
        asm volatile("cp.async.wait_group 0;");
        __syncthreads();

        const uint32_t aH = sbase + (uint32_t)(mw * 32) * kPadB + aRowOff;
        const uint32_t bH = sbase + 2 * kArrB + (uint32_t)(nw * 64) * kPadB + bOff;
#pragma unroll
        for (int ks = 0; ks < 4; ks++) {
            const uint32_t kb = ks * 32;
            uint32_t ah[2][4], al[2][4];
#pragma unroll
            for (int mt = 0; mt < 2; mt++) {
                LDSM4(ah[mt], aH + mt * 2304 + kb);
                LDSM4(al[mt], aH + kArrB + mt * 2304 + kb);
            }
#pragma unroll
            for (int ntp = 0; ntp < 4; ntp++) {
                uint32_t bh[4], bl[4];
                LDSM4(bh, bH + ntp * 2304 + kb);
                LDSM4(bl, bH + kArrB + ntp * 2304 + kb);
#pragma unroll
                for (int mt = 0; mt < 2; mt++) {
                    mma16816(acc[mt][2 * ntp], ah[mt], bh);
                    mma16816(acc[mt][2 * ntp], ah[mt], bl);
                    mma16816(acc[mt][2 * ntp], al[mt], bh);
                    mma16816(acc[mt][2 * ntp + 1], ah[mt], bh + 2);
                    mma16816(acc[mt][2 * ntp + 1], ah[mt], bl + 2);
                    mma16816(acc[mt][2 * ntp + 1], al[mt], bh + 2);
                }
            }
        }
        __syncthreads();
    }

    if (OUT == 2) {
        float* Cs = (float*)smem;
#pragma unroll
        for (int mt = 0; mt < 2; mt++) {
#pragma unroll
            for (int nt = 0; nt < 8; nt++) {
                const int col = nw * 64 + nt * 8 + tig * 2;
                const float b0 = bias[col], b1 = bias[col + 1];
                const int r0 = mw * 32 + mt * 16 + g;
                Cs[r0 * kLnStride + col]           = acc[mt][nt][0] + b0;
                Cs[r0 * kLnStride + col + 1]       = acc[mt][nt][1] + b1;
                Cs[(r0 + 8) * kLnStride + col]     = acc[mt][nt][2] + b0;
                Cs[(r0 + 8) * kLnStride + col + 1] = acc[mt][nt][3] + b1;
            }
        }
        __syncthreads();
        const float4 g4 = *(const float4*)&gamma[lane * 4];
        const float4 be4 = *(const float4*)&beta[lane * 4];
#pragma unroll 2
        for (int rr = 0; rr < 16; rr++) {
            const int row = wid * 16 + rr;
            const size_t grow = (size_t)(m0 + row) * 128 + lane * 4;
            float4 v = *(float4*)&Cs[row * kLnStride + lane * 4];
            const float4 rs4 = *(const float4*)&resid[grow];
            v.x += rs4.x; v.y += rs4.y; v.z += rs4.z; v.w += rs4.w;
            float s = v.x + v.y + v.z + v.w;
#pragma unroll
            for (int o = 16; o > 0; o >>= 1) s += __shfl_xor_sync(~0u, s, o);
            const float mean = s * (1.f / 128.f);
            float dx = v.x - mean, dy = v.y - mean, dz = v.z - mean,
                  dw = v.w - mean;
            float ss = dx * dx + dy * dy + dz * dz + dw * dw;
#pragma unroll
            for (int o = 16; o > 0; o >>= 1) ss += __shfl_xor_sync(~0u, ss, o);
            const float rstd = rsqrtf(ss * (1.f / 128.f) + 1e-5f);
            float4 ov;
            ov.x = dx * rstd * g4.x + be4.x;
            ov.y = dy * rstd * g4.y + be4.y;
            ov.z = dz * rstd * g4.z + be4.z;
            ov.w = dw * rstd * g4.w + be4.w;
            *(float4*)&C[grow] = ov;
            __nv_bfloat162 h0, l0, h1, l1;
            split2(ov.x, h0.x, l0.x); split2(ov.y, h0.y, l0.y);
            split2(ov.z, h1.x, l1.x); split2(ov.w, h1.y, l1.y);
            *(__nv_bfloat162*)&Ch[grow] = h0;
            *(__nv_bfloat162*)&Ch[grow + 2] = h1;
            *(__nv_bfloat162*)&Cl[grow] = l0;
            *(__nv_bfloat162*)&Cl[grow + 2] = l1;
        }
        return;
    }

#pragma unroll
    for (int mt = 0; mt < 2; mt++) {
#pragma unroll
        for (int nt = 0; nt < 8; nt++) {
            const int col = n0 + nw * 64 + nt * 8 + tig * 2;
            const float b0 = bias[col], b1 = bias[col + 1];
            const int r0 = m0 + mw * 32 + mt * 16 + g;
            float v00 = acc[mt][nt][0] + b0, v01 = acc[mt][nt][1] + b1;
            float v10 = acc[mt][nt][2] + b0, v11 = acc[mt][nt][3] + b1;
            if (OUT == 1 || OUT == 3) {
                if (OUT == 1) {
                    v00 = fmaxf(v00, 0.f); v01 = fmaxf(v01, 0.f);
                    v10 = fmaxf(v10, 0.f); v11 = fmaxf(v11, 0.f);
                }
                __nv_bfloat162 h0, l0, h1, l1;
                split2(v00, h0.x, l0.x); split2(v01, h0.y, l0.y);
                split2(v10, h1.x, l1.x); split2(v11, h1.y, l1.y);
                *(__nv_bfloat162*)&Ch[(size_t)r0 * N + col] = h0;
                *(__nv_bfloat162*)&Cl[(size_t)r0 * N + col] = l0;
                *(__nv_bfloat162*)&Ch[(size_t)(r0 + 8) * N + col] = h1;
                *(__nv_bfloat162*)&Cl[(size_t)(r0 + 8) * N + col] = l1;
            } else {
                *(float2*)&C[(size_t)r0 * N + col] = {v00, v01};
                *(float2*)&C[(size_t)(r0 + 8) * N + col] = {v10, v11};
            }
        }
    }
}

// ---------------- hist projection + positional encoding -------------------
__global__ __launch_bounds__(256) void hist_pe_kernel(
        const float* __restrict__ feat, const float* __restrict__ w,
        const float* __restrict__ bias) {
    int idx = blockIdx.x * 256 + threadIdx.x;
    int row = idx >> 7, d = idx & 127;
    float f0 = feat[row * 3 + 0], f1 = feat[row * 3 + 1], f2 = feat[row * 3 + 2];
    float x = f0 * w[d] + f1 * w[kD + d] + f2 * w[2 * kD + d] + bias[d];
    g_x[idx] = x;
    int t = row & (kT - 1);
    float e = x + g_pet[t * kD + d];
    g_e[idx] = e;
    __nv_bfloat16 h, l;
    split2(e, h, l);
    g_eh[idx] = h;
    g_el[idx] = l;
}

// ---------------- tensor-core attention: 1 warp per (bn, head) -------------
static constexpr int kAStr = 24;   // bf16 elems per smem row (48B, aligned)

__global__ __launch_bounds__(64) void attn_mma_kernel() {
    const int bn = blockIdx.x;
    const int w = threadIdx.x >> 5, lane = threadIdx.x & 31;
    const int h = blockIdx.y * 2 + w;
    const int g = lane >> 2, tig = lane & 3;
    __shared__ __nv_bfloat16 sKV[2][4][128 * kAStr];  // [warp][Kh,Kl,Vh,Vl]

    {
        const int colK = 128 + h * 16, colV = 256 + h * 16;
#pragma unroll
        for (int a = 0; a < 4; a++) {
            const __nv_bfloat16* src = (a & 1) ? g_qkvl : g_qkvh;
            const int col = (a < 2) ? colK : colV;
            __nv_bfloat16* dst = sKV[w][a];
#pragma unroll
            for (int i = lane; i < 256; i += 32) {
                int row = i >> 1, half = i & 1;
                *(uint4*)&dst[row * kAStr + half * 8] =
                    *(const uint4*)&src[(size_t)(bn * 128 + row) * 384 + col + half * 8];
            }
        }
    }
    __syncwarp();

    uint32_t kvb[4];
#pragma unroll
    for (int a = 0; a < 4; a++)
        kvb[a] = (uint32_t)__cvta_generic_to_shared(&sKV[w][a][0]);

    const uint32_t offK = (uint32_t)((lane & 7) * 48 + ((lane >> 3) & 1) * 16);
    const uint32_t offV = (uint32_t)(((lane & 7) + ((lane >> 3) & 1) * 8) * 48);

    for (int mt = 0; mt < 8; mt++) {
        const size_t r0 = (size_t)(bn * 128 + mt * 16 + g) * 384 + h * 16 + tig * 2;
        const size_t r1 = r0 + 8 * 384;
        uint32_t qh[4], ql[4];
        qh[0] = *(const uint32_t*)&g_qkvh[r0];
        qh[1] = *(const uint32_t*)&g_qkvh[r1];
        qh[2] = *(const uint32_t*)&g_qkvh[r0 + 8];
        qh[3] = *(const uint32_t*)&g_qkvh[r1 + 8];
        ql[0] = *(const uint32_t*)&g_qkvl[r0];
        ql[1] = *(const uint32_t*)&g_qkvl[r1];
        ql[2] = *(const uint32_t*)&g_qkvl[r0 + 8];
        ql[3] = *(const uint32_t*)&g_qkvl[r1 + 8];

        float c[16][4];
#pragma unroll
        for (int j = 0; j < 16; j++)
#pragma unroll
            for (int t = 0; t < 4; t++) c[j][t] = 0.f;

#pragma unroll
        for (int j = 0; j < 16; j++) {
            uint32_t kh[2], kl[2];
            LDSM2(kh, kvb[0] + j * 384 + offK);
            LDSM2(kl, kvb[1] + j * 384 + offK);
            mma16816(c[j], qh, kh);
            mma16816(c[j], qh, kl);
            mma16816(c[j], ql, kh);
        }

        float mx0 = -1e30f, mx1 = -1e30f;
#pragma unroll
        for (int j = 0; j < 16; j++) {
            c[j][0] *= 0.25f; c[j][1] *= 0.25f;
            c[j][2] *= 0.25f; c[j][3] *= 0.25f;
            mx0 = fmaxf(mx0, fmaxf(c[j][0], c[j][1]));
            mx1 = fmaxf(mx1, fmaxf(c[j][2], c[j][3]));
        }
        mx0 = fmaxf(mx0, __shfl_xor_sync(~0u, mx0, 1));
        mx0 = fmaxf(mx0, __shfl_xor_sync(~0u, mx0, 2));
        mx1 = fmaxf(mx1, __shfl_xor_sync(~0u, mx1, 1));
        mx1 = fmaxf(mx1, __shfl_xor_sync(~0u, mx1, 2));
        float sm0 = 0.f, sm1 = 0.f;
#pragma unroll
        for (int j = 0; j < 16; j++) {
            c[j][0] = __expf(c[j][0] - mx0); sm0 += c[j][0];
            c[j][1] = __expf(c[j][1] - mx0); sm0 += c[j][1];
            c[j][2] = __expf(c[j][2] - mx1); sm1 += c[j][2];
            c[j][3] = __expf(c[j][3] - mx1); sm1 += c[j][3];
        }
        sm0 += __shfl_xor_sync(~0u, sm0, 1);
        sm0 += __shfl_xor_sync(~0u, sm0, 2);
        sm1 += __shfl_xor_sync(~0u, sm1, 1);
        sm1 += __shfl_xor_sync(~0u, sm1, 2);

        float o[2][4];
#pragma unroll
        for (int n = 0; n < 2; n++)
#pragma unroll
            for (int t = 0; t < 4; t++) o[n][t] = 0.f;

#pragma unroll
        for (int ks = 0; ks < 8; ks++) {
            uint32_t ph[4], pl[4];
#pragma unroll
            for (int half = 0; half < 2; half++) {
                const float* cv = c[2 * ks + half];
                __nv_bfloat162 h01, l01, h23, l23;
                split2(cv[0], h01.x, l01.x); split2(cv[1], h01.y, l01.y);
                split2(cv[2], h23.x, l23.x); split2(cv[3], h23.y, l23.y);
                ph[half * 2 + 0] = *(uint32_t*)&h01;
                ph[half * 2 + 1] = *(uint32_t*)&h23;
                pl[half * 2 + 0] = *(uint32_t*)&l01;
                pl[half * 2 + 1] = *(uint32_t*)&l23;
            }
            uint32_t pha[4] = {ph[0], ph[1], ph[2], ph[3]};
            uint32_t pla[4] = {pl[0], pl[1], pl[2], pl[3]};
#pragma unroll
            for (int n = 0; n < 2; n++) {
                uint32_t vh[2], vl[2];
                LDSM2T(vh, kvb[2] + ks * 768 + offV + n * 16);
                LDSM2T(vl, kvb[3] + ks * 768 + offV + n * 16);
                mma16816(o[n], pha, vh);
                mma16816(o[n], pha, vl);
                mma16816(o[n], pla, vh);
            }
        }

        const float i0 = 1.f / sm0, i1 = 1.f / sm1;
        const size_t ro = (size_t)(bn * 128 + mt * 16 + g) * 128 + h * 16;
#pragma unroll
        for (int n = 0; n < 2; n++) {
            const size_t cA = ro + n * 8 + tig * 2;
            const size_t cB = cA + 8 * 128;
            __nv_bfloat162 h0, l0, h1, l1;
            split2(o[n][0] * i0, h0.x, l0.x);
            split2(o[n][1] * i0, h0.y, l0.y);
            split2(o[n][2] * i1, h1.x, l1.x);
            split2(o[n][3] * i1, h1.y, l1.y);
            *(__nv_bfloat162*)&g_aoh[cA] = h0;
            *(__nv_bfloat162*)&g_aol[cA] = l0;
            *(__nv_bfloat162*)&g_aoh[cB] = h1;
            *(__nv_bfloat162*)&g_aol[cB] = l1;
        }
    }
}

// ---------------- node score: warp per row ---------------------------------
__global__ __launch_bounds__(256) void s_kernel() {
    const int wid = threadIdx.x >> 5, lane = threadIdx.x & 31;
    const int row = blockIdx.x * 8 + wid;
    const float4 e4 = *(const float4*)&g_e[(size_t)row * kD + lane * 4];
    const float4 x4 = *(const float4*)&g_x[(size_t)row * kD + lane * 4];
    float p = e4.x * x4.x + e4.y * x4.y + e4.z * x4.z + e4.w * x4.w;
#pragma unroll
    for (int o = 16; o > 0; o >>= 1) p += __shfl_xor_sync(~0u, p, o);
    if (lane == 0) {
        int b = row >> 13;
        int rem = row & 8191;
        int n = rem >> 7, tt = rem & 127;
        g_s[b * kNN + tt * kNA + n] = p;
    }
}

// ---------------- edge segment-sum ----------------------------------------
__global__ void edge_kernel(const int* __restrict__ ei,
                            const float* __restrict__ ew) {
    int idx = blockIdx.x * blockDim.x + threadIdx.x;
    if (idx >= kB * kE) return;
    int b = idx / kE, e = idx - b * kE;
    int src = ei[b * 2 * kE + e];
    int dst = ei[b * 2 * kE + kE + e];
    atomicAdd(&g_gout[b * kNN + dst], ew[idx] * g_s[b * kNN + src]);
}

// ---------------- global mean/var over gout -------------------------------
__global__ __launch_bounds__(256) void stats_kernel() {
    int i = blockIdx.x * blockDim.x + threadIdx.x;
    double s = 0.0, s2 = 0.0;
    for (int k = i; k < kB * kNN; k += gridDim.x * blockDim.x) {
        double v = (double)g_gout[k];
        s += v; s2 += v * v;
    }
#pragma unroll
    for (int o = 16; o > 0; o >>= 1) {
        s  += __shfl_xor_sync(~0u, s, o);
        s2 += __shfl_xor_sync(~0u, s2, o);
    }
    __shared__ double ws[8][2];
    int w = threadIdx.x >> 5;
    if ((threadIdx.x & 31) == 0) { ws[w][0] = s; ws[w][1] = s2; }
    __syncthreads();
    if (threadIdx.x == 0) {
        double a = 0, b2 = 0;
        for (int k = 0; k < 8; k++) { a += ws[k][0]; b2 += ws[k][1]; }
        atomicAdd(&g_red[0], a);
        atomicAdd(&g_red[1], b2);
    }
}

// ---------------- batchnorm + rank-1 output --------------------------------
__global__ void out_kernel(const float* __restrict__ bng,
                           const float* __restrict__ bnb,
                           const float* __restrict__ lw,
                           const float* __restrict__ lb,
                           float* __restrict__ out) {
    int idx = blockIdx.x * blockDim.x + threadIdx.x;
    if (idx >= kRows * kD) return;
    int d = idx & 127;
    int t = (idx >> 7) & 127;
    int n = (idx >> 14) & 63;
    int b = idx >> 20;
    const double inv_n = 1.0 / (double)(kB * kNN);
    double m = g_red[0] * inv_n;
    double var = g_red[1] * inv_n - m * m;
    double rs = 1.0 / sqrt(var + 1e-5);
    float gv = g_gout[b * kNN + t * kNA + n];
    float norm = (float)(((double)gv - m) * rs) * bng[0] + bnb[0];
    out[idx] = norm * lw[d] + lb[d];
}

// ---------------- launch ---------------------------------------------------
extern "C" void kernel_launch(void* const* d_in, const int* in_sizes, int n_in,
                              void* d_out, int out_size) {
    const float* feat  = (const float*)d_in[0];
    const int*   eidx  = (const int*)d_in[1];
    const float* ew    = (const float*)d_in[2];
    const float* histw = (const float*)d_in[3];
    const float* histb = (const float*)d_in[4];
    const float* wq    = (const float*)d_in[5];
    const float* bq    = (const float*)d_in[6];
    const float* wk    = (const float*)d_in[7];
    const float* bk    = (const float*)d_in[8];
    const float* wv    = (const float*)d_in[9];
    const float* bv    = (const float*)d_in[10];
    const float* wo    = (const float*)d_in[11];
    const float* bo    = (const float*)d_in[12];
    const float* ln1g  = (const float*)d_in[13];
    const float* ln1b  = (const float*)d_in[14];
    const float* fw1   = (const float*)d_in[15];
    const float* fb1   = (const float*)d_in[16];
    const float* fw2   = (const float*)d_in[17];
    const float* fb2   = (const float*)d_in[18];
    const float* ln2g  = (const float*)d_in[19];
    const float* ln2b  = (const float*)d_in[20];
    const float* bng   = (const float*)d_in[21];
    const float* bnb   = (const float*)d_in[22];
    const float* lgw   = (const float*)d_in[23];
    const float* lgb   = (const float*)d_in[24];
    float* out = (float*)d_out;

    float *pe, *ph1, *pbqkv;
    __nv_bfloat16 *pwh, *pwl, *peh, *pel, *paoh, *paol, *ph1h, *ph1l, *pffh, *pffl,
                  *pqkvh, *pqkvl;
    cudaGetSymbolAddress((void**)&pe,   g_e);
    cudaGetSymbolAddress((void**)&ph1,  g_h1);
    cudaGetSymbolAddress((void**)&pwh,  g_wth);
    cudaGetSymbolAddress((void**)&pwl,  g_wtl);
    cudaGetSymbolAddress((void**)&pbqkv, g_bqkv);
    cudaGetSymbolAddress((void**)&peh,  g_eh);
    cudaGetSymbolAddress((void**)&pel,  g_el);
    cudaGetSymbolAddress((void**)&paoh, g_aoh);
    cudaGetSymbolAddress((void**)&paol, g_aol);
    cudaGetSymbolAddress((void**)&ph1h, g_h1h);
    cudaGetSymbolAddress((void**)&ph1l, g_h1l);
    cudaGetSymbolAddress((void**)&pffh, g_ffh);
    cudaGetSymbolAddress((void**)&pffl, g_ffl);
    cudaGetSymbolAddress((void**)&pqkvh, g_qkvh);
    cudaGetSymbolAddress((void**)&pqkvl, g_qkvl);

    cudaFuncSetAttribute(gemm_mma<0>,
                         cudaFuncAttributeMaxDynamicSharedMemorySize, kGemmSmem);
    cudaFuncSetAttribute(gemm_mma<1>,
                         cudaFuncAttributeMaxDynamicSharedMemorySize, kGemmSmem);
    cudaFuncSetAttribute(gemm_mma<2>,
                         cudaFuncAttributeMaxDynamicSharedMemorySize, kGemmSmem);
    cudaFuncSetAttribute(gemm_mma<3>,
                         cudaFuncAttributeMaxDynamicSharedMemorySize, kGemmSmem);

    // launch order matters for ncu (-s 5 -c 1 profiles launch #6 = O-proj GEMM)
    setup_kernel<<<(kB * kNN + 255) / 256, 256>>>(bq, bk, bv);
    wconv_all<<<(kL * kWL + 255) / 256, 256>>>(wq, wk, wv, wo, fw1, fw2);
    hist_pe_kernel<<<kRows * kD / 256, 256>>>(feat, histw, histb);

    const int MT = kRows / 128;  // 256 M tiles
    for (int l = 0; l < kL; l++) {
        const int base = l * kWL;
        // QKV fused: N=384, K=128 -> bf16 splits
        gemm_mma<3><<<dim3(3, MT), 256, kGemmSmem>>>(
            peh, pel, pwh + base, pwl + base, pbqkv + l * 384,
            nullptr, pqkvh, pqkvl, nullptr, nullptr, nullptr, 384, 128);
        attn_mma_kernel<<<dim3(kB * kNA, kH / 2), 64>>>();
        // O proj + residual(e) + LN1 -> h1 (f32 + splits)
        gemm_mma<2><<<dim3(1, MT), 256, kGemmSmem>>>(
            paoh, paol, pwh + base + 49152, pwl + base + 49152, bo + l * kD,
            ph1, ph1h, ph1l, pe, ln1g + l * kD, ln1b + l * kD, 128, 128);
        // FF1: N=512, K=128, relu + split out
        gemm_mma<1><<<dim3(4, MT), 256, kGemmSmem>>>(
            ph1h, ph1l, pwh + base + 65536, pwl + base + 65536, fb1 + l * kDFF,
            nullptr, pffh, pffl, nullptr, nullptr, nullptr, 512, 128);
        // FF2 + residual(h1) + LN2 -> e (f32 + splits)
        gemm_mma<2><<<dim3(1, MT), 256, kGemmSmem>>>(
            pffh, pffl, pwh + base + 131072, pwl + base + 131072, fb2 + l * kD,
            pe, peh, pel, ph1, ln2g + l * kD, ln2b + l * kD, 128, 512);
    }

    s_kernel<<<kRows / 8, 256>>>();
    edge_kernel<<<(kB * kE + 255) / 256, 256>>>(eidx, ew);
    stats_kernel<<<64, 256>>>();
    out_kernel<<<(kRows * kD + 255) / 256, 256>>>(bng, bnb, lgw, lgb, out);
}

// round 14
// speedup vs baseline: 1.1512x; 1.1214x over previous
#include <cuda_runtime.h>
#include <cuda_bf16.h>
#include <math.h>
#include <stdint.h>

static constexpr int kB = 4, kNA = 64, kT = 128, kD = 128, kH = 8, kL = 3;
static constexpr int kDFF = 512, kE = 65536, kNN = kT * kNA, kDH = kD / kH;
static constexpr int kRows = kB * kNA * kT;   // 32768

// ---------------- scratch (device globals; no runtime allocation) ----------
__device__ float g_x  [kRows * kD];
__device__ float g_e  [kRows * kD];
__device__ float g_h1 [kRows * kD];
__device__ float g_pet[kT * kD];
__device__ float g_s   [kB * kNN];
__device__ float g_gout[kB * kNN];
__device__ double g_red[2];

// bf16 hi/lo split activations
__device__ __nv_bfloat16 g_eh [kRows * kD],  g_el [kRows * kD];
__device__ __nv_bfloat16 g_qkvh[kRows * 384], g_qkvl[kRows * 384];
__device__ __nv_bfloat16 g_aoh[kRows * kD],  g_aol[kRows * kD];
__device__ __nv_bfloat16 g_h1h[kRows * kD],  g_h1l[kRows * kD];
__device__ __nv_bfloat16 g_ffh[kRows * kDFF], g_ffl[kRows * kDFF];

// transposed bf16-split weights, per layer block of 196608 elems:
//   [0] QKV^T 384x128 | [49152] O^T 128x128 | [65536] FF1^T 512x128 | [131072] FF2^T 128x512
static constexpr int kWL = 196608;
__device__ __nv_bfloat16 g_wth[kL * kWL];
__device__ __nv_bfloat16 g_wtl[kL * kWL];
__device__ float g_bqkv[kL * 384];

__device__ __forceinline__ void split2(float x, __nv_bfloat16& h, __nv_bfloat16& l) {
    h = __float2bfloat16(x);
    l = __float2bfloat16(x - __bfloat162float(h));
}

// ====================== fused setup: zero + PE table + qkv bias ============
__global__ __launch_bounds__(256) void setup_kernel(
        const float* __restrict__ bq, const float* __restrict__ bk,
        const float* __restrict__ bv) {
    int i = blockIdx.x * 256 + threadIdx.x;
    if (i < kB * kNN) g_gout[i] = 0.f;
    if (i < 2) g_red[i] = 0.0;
    if (i < kT * kD) {
        int t = i >> 7, d = i & 127;
        int j = d >> 1;
        float freq = expf(-9.210340371976184f * (float)(2 * j) / (float)kD);
        float ang = (float)t * freq;
        g_pet[i] = (d & 1) ? cosf(ang) : sinf(ang);
    }
    if (i < kL * 384) {
        int l = i / 384, j = i - l * 384;
        float v = (j < 128) ? bq[l * 128 + j]
                : (j < 256) ? bk[l * 128 + j - 128]
                            : bv[l * 128 + j - 256];
        g_bqkv[i] = v;
    }
}

// ====================== fused weight conversion ============================
__global__ __launch_bounds__(256) void wconv_all(
        const float* __restrict__ wq, const float* __restrict__ wk,
        const float* __restrict__ wv, const float* __restrict__ wo,
        const float* __restrict__ fw1, const float* __restrict__ fw2) {
    int i = blockIdx.x * blockDim.x + threadIdx.x;
    if (i >= kL * kWL) return;
    int l = i / kWL, off = i - l * kWL;
    const float* W; int N, n, k;
    if (off < 49152) {
        int m = off >> 14, o2 = off & 16383;
        W = (m == 0 ? wq : m == 1 ? wk : wv) + l * 16384;
        n = o2 >> 7; k = o2 & 127; N = 128;
    } else if (off < 65536) {
        int o2 = off - 49152;
        W = wo + l * 16384; n = o2 >> 7; k = o2 & 127; N = 128;
    } else if (off < 131072) {
        int o2 = off - 65536;
        W = fw1 + l * 65536; n = o2 >> 7; k = o2 & 127; N = 512;
    } else {
        int o2 = off - 131072;
        W = fw2 + l * 65536; n = o2 >> 9; k = o2 & 511; N = 128;
    }
    __nv_bfloat16 h, lo;
    split2(W[(size_t)k * N + n], h, lo);
    g_wth[i] = h; g_wtl[i] = lo;
}

// ====================== bf16-split MMA GEMM ================================
// Single buffer, K chunk 64. __launch_bounds__(256,2) caps regs at 128 so the
// register file (not smem) allows 2 CTAs/SM: profiled regs=170 -> occ 12%.
static constexpr int kPadB = 144;
static constexpr int kArrB = 128 * kPadB;      // 18432
static constexpr int kBufB = 4 * kArrB;        // 73728
static constexpr int kGemmSmem = kBufB;
static constexpr int kLnStride = 132;

#define LDSM4(r, addr) \
    asm volatile("ldmatrix.sync.aligned.m8n8.x4.shared.b16 {%0,%1,%2,%3}, [%4];" \
        : "=r"((r)[0]), "=r"((r)[1]), "=r"((r)[2]), "=r"((r)[3]) : "r"(addr))
#define LDSM2(r, addr) \
    asm volatile("ldmatrix.sync.aligned.m8n8.x2.shared.b16 {%0,%1}, [%2];" \
        : "=r"((r)[0]), "=r"((r)[1]) : "r"(addr))
#define LDSM2T(r, addr) \
    asm volatile("ldmatrix.sync.aligned.m8n8.x2.trans.shared.b16 {%0,%1}, [%2];" \
        : "=r"((r)[0]), "=r"((r)[1]) : "r"(addr))

__device__ __forceinline__ void mma16816(float* c, const uint32_t* a,
                                         const uint32_t* b) {
    asm volatile(
        "mma.sync.aligned.m16n8k16.row.col.f32.bf16.bf16.f32 "
        "{%0,%1,%2,%3}, {%4,%5,%6,%7}, {%8,%9}, {%0,%1,%2,%3};"
        : "+f"(c[0]), "+f"(c[1]), "+f"(c[2]), "+f"(c[3])
        : "r"(a[0]), "r"(a[1]), "r"(a[2]), "r"(a[3]), "r"(b[0]), "r"(b[1]));
}

// OUT: 0 f32+bias | 1 relu+split | 2 residual+LN | 3 split (no relu)
template <int OUT>
__global__ __launch_bounds__(256, 2) void gemm_mma(
        const __nv_bfloat16* __restrict__ Ahg, const __nv_bfloat16* __restrict__ Alg,
        const __nv_bfloat16* __restrict__ Bhg, const __nv_bfloat16* __restrict__ Blg,
        const float* __restrict__ bias, float* __restrict__ C,
        __nv_bfloat16* __restrict__ Ch, __nv_bfloat16* __restrict__ Cl,
        const float* __restrict__ resid, const float* __restrict__ gamma,
        const float* __restrict__ beta, int N, int K) {
    extern __shared__ char smem[];
    const uint32_t sbase = (uint32_t)__cvta_generic_to_shared(smem);
    const int tid = threadIdx.x;
    const int wid = tid >> 5, lane = tid & 31;
    const int g = lane >> 2, tig = lane & 3;
    const int mw = wid >> 1, nw = wid & 1;
    const int m0 = blockIdx.y * 128, n0 = blockIdx.x * 128;

    float acc[2][8][4];
#pragma unroll
    for (int i = 0; i < 2; i++)
#pragma unroll
        for (int j = 0; j < 8; j++)
#pragma unroll
            for (int t = 0; t < 4; t++) acc[i][j][t] = 0.f;

    const int stages = K >> 6;
    const uint32_t aRowOff = (uint32_t)((lane & 15) * kPadB + (lane >> 4) * 16);
    const int bRow = (lane & 7) + ((lane >> 4) & 1) * 8;
    const uint32_t bOff = (uint32_t)(bRow * kPadB + ((lane >> 3) & 1) * 16);

    for (int s = 0; s < stages; s++) {
#pragma unroll
        for (int it = 0; it < 16; it++) {
            const int arr = it >> 2;
            const int j = tid + ((it & 3) << 8);
            const int r = j >> 3, c = j & 7;
            const __nv_bfloat16* gp;
            if (arr == 0)      gp = Ahg + (size_t)(m0 + r) * K + (s << 6) + c * 8;
            else if (arr == 1) gp = Alg + (size_t)(m0 + r) * K + (s << 6) + c * 8;
            else if (arr == 2) gp = Bhg + (size_t)(n0 + r) * K + (s << 6) + c * 8;
            else               gp = Blg + (size_t)(n0 + r) * K + (s << 6) + c * 8;
            uint32_t dp = sbase + arr * kArrB + r * kPadB + c * 16;
            asm volatile("cp.async.ca.shared.global [%0], [%1], 16;"
                         :: "r"(dp), "l"(gp));
        }
        asm volatile("cp.async.commit_group;");
        asm volatile("cp.async.wait_group 0;");
        __syncthreads();

        const uint32_t aH = sbase + (uint32_t)(mw * 32) * kPadB + aRowOff;
        const uint32_t bH = sbase + 2 * kArrB + (uint32_t)(nw * 64) * kPadB + bOff;
#pragma unroll
        for (int ks = 0; ks < 4; ks++) {
            const uint32_t kb = ks * 32;
            // phase 1: ah against bh+bl (al not yet live)
            uint32_t ah[2][4];
#pragma unroll
            for (int mt = 0; mt < 2; mt++)
                LDSM4(ah[mt], aH + mt * 2304 + kb);
#pragma unroll
            for (int ntp = 0; ntp < 4; ntp++) {
                uint32_t bh[4], bl[4];
                LDSM4(bh, bH + ntp * 2304 + kb);
                LDSM4(bl, bH + kArrB + ntp * 2304 + kb);
#pragma unroll
                for (int mt = 0; mt < 2; mt++) {
                    mma16816(acc[mt][2 * ntp], ah[mt], bh);
                    mma16816(acc[mt][2 * ntp], ah[mt], bl);
                    mma16816(acc[mt][2 * ntp + 1], ah[mt], bh + 2);
                    mma16816(acc[mt][2 * ntp + 1], ah[mt], bl + 2);
                }
            }
            // phase 2: al against bh only
            uint32_t al[2][4];
#pragma unroll
            for (int mt = 0; mt < 2; mt++)
                LDSM4(al[mt], aH + kArrB + mt * 2304 + kb);
#pragma unroll
            for (int ntp = 0; ntp < 4; ntp++) {
                uint32_t bh[4];
                LDSM4(bh, bH + ntp * 2304 + kb);
#pragma unroll
                for (int mt = 0; mt < 2; mt++) {
                    mma16816(acc[mt][2 * ntp], al[mt], bh);
                    mma16816(acc[mt][2 * ntp + 1], al[mt], bh + 2);
                }
            }
        }
        __syncthreads();
    }

    if (OUT == 2) {
        float* Cs = (float*)smem;
#pragma unroll
        for (int mt = 0; mt < 2; mt++) {
#pragma unroll
            for (int nt = 0; nt < 8; nt++) {
                const int col = nw * 64 + nt * 8 + tig * 2;
                const float b0 = bias[col], b1 = bias[col + 1];
                const int r0 = mw * 32 + mt * 16 + g;
                Cs[r0 * kLnStride + col]           = acc[mt][nt][0] + b0;
                Cs[r0 * kLnStride + col + 1]       = acc[mt][nt][1] + b1;
                Cs[(r0 + 8) * kLnStride + col]     = acc[mt][nt][2] + b0;
                Cs[(r0 + 8) * kLnStride + col + 1] = acc[mt][nt][3] + b1;
            }
        }
        __syncthreads();
        const float4 g4 = *(const float4*)&gamma[lane * 4];
        const float4 be4 = *(const float4*)&beta[lane * 4];
#pragma unroll 2
        for (int rr = 0; rr < 16; rr++) {
            const int row = wid * 16 + rr;
            const size_t grow = (size_t)(m0 + row) * 128 + lane * 4;
            float4 v = *(float4*)&Cs[row * kLnStride + lane * 4];
            const float4 rs4 = *(const float4*)&resid[grow];
            v.x += rs4.x; v.y += rs4.y; v.z += rs4.z; v.w += rs4.w;
            float s = v.x + v.y + v.z + v.w;
#pragma unroll
            for (int o = 16; o > 0; o >>= 1) s += __shfl_xor_sync(~0u, s, o);
            const float mean = s * (1.f / 128.f);
            float dx = v.x - mean, dy = v.y - mean, dz = v.z - mean,
                  dw = v.w - mean;
            float ss = dx * dx + dy * dy + dz * dz + dw * dw;
#pragma unroll
            for (int o = 16; o > 0; o >>= 1) ss += __shfl_xor_sync(~0u, ss, o);
            const float rstd = rsqrtf(ss * (1.f / 128.f) + 1e-5f);
            float4 ov;
            ov.x = dx * rstd * g4.x + be4.x;
            ov.y = dy * rstd * g4.y + be4.y;
            ov.z = dz * rstd * g4.z + be4.z;
            ov.w = dw * rstd * g4.w + be4.w;
            *(float4*)&C[grow] = ov;
            __nv_bfloat162 h0, l0, h1, l1;
            split2(ov.x, h0.x, l0.x); split2(ov.y, h0.y, l0.y);
            split2(ov.z, h1.x, l1.x); split2(ov.w, h1.y, l1.y);
            *(__nv_bfloat162*)&Ch[grow] = h0;
            *(__nv_bfloat162*)&Ch[grow + 2] = h1;
            *(__nv_bfloat162*)&Cl[grow] = l0;
            *(__nv_bfloat162*)&Cl[grow + 2] = l1;
        }
        return;
    }

#pragma unroll
    for (int mt = 0; mt < 2; mt++) {
#pragma unroll
        for (int nt = 0; nt < 8; nt++) {
            const int col = n0 + nw * 64 + nt * 8 + tig * 2;
            const float b0 = bias[col], b1 = bias[col + 1];
            const int r0 = m0 + mw * 32 + mt * 16 + g;
            float v00 = acc[mt][nt][0] + b0, v01 = acc[mt][nt][1] + b1;
            float v10 = acc[mt][nt][2] + b0, v11 = acc[mt][nt][3] + b1;
            if (OUT == 1 || OUT == 3) {
                if (OUT == 1) {
                    v00 = fmaxf(v00, 0.f); v01 = fmaxf(v01, 0.f);
                    v10 = fmaxf(v10, 0.f); v11 = fmaxf(v11, 0.f);
                }
                __nv_bfloat162 h0, l0, h1, l1;
                split2(v00, h0.x, l0.x); split2(v01, h0.y, l0.y);
                split2(v10, h1.x, l1.x); split2(v11, h1.y, l1.y);
                *(__nv_bfloat162*)&Ch[(size_t)r0 * N + col] = h0;
                *(__nv_bfloat162*)&Cl[(size_t)r0 * N + col] = l0;
                *(__nv_bfloat162*)&Ch[(size_t)(r0 + 8) * N + col] = h1;
                *(__nv_bfloat162*)&Cl[(size_t)(r0 + 8) * N + col] = l1;
            } else {
                *(float2*)&C[(size_t)r0 * N + col] = {v00, v01};
                *(float2*)&C[(size_t)(r0 + 8) * N + col] = {v10, v11};
            }
        }
    }
}

// ---------------- hist projection + positional encoding -------------------
__global__ __launch_bounds__(256) void hist_pe_kernel(
        const float* __restrict__ feat, const float* __restrict__ w,
        const float* __restrict__ bias) {
    int idx = blockIdx.x * 256 + threadIdx.x;
    int row = idx >> 7, d = idx & 127;
    float f0 = feat[row * 3 + 0], f1 = feat[row * 3 + 1], f2 = feat[row * 3 + 2];
    float x = f0 * w[d] + f1 * w[kD + d] + f2 * w[2 * kD + d] + bias[d];
    g_x[idx] = x;
    int t = row & (kT - 1);
    float e = x + g_pet[t * kD + d];
    g_e[idx] = e;
    __nv_bfloat16 h, l;
    split2(e, h, l);
    g_eh[idx] = h;
    g_el[idx] = l;
}

// ---------------- tensor-core attention: 1 warp per (bn, head) -------------
static constexpr int kAStr = 24;   // bf16 elems per smem row (48B, aligned)

__global__ __launch_bounds__(64) void attn_mma_kernel() {
    const int bn = blockIdx.x;
    const int w = threadIdx.x >> 5, lane = threadIdx.x & 31;
    const int h = blockIdx.y * 2 + w;
    const int g = lane >> 2, tig = lane & 3;
    __shared__ __nv_bfloat16 sKV[2][4][128 * kAStr];  // [warp][Kh,Kl,Vh,Vl]

    {
        const int colK = 128 + h * 16, colV = 256 + h * 16;
#pragma unroll
        for (int a = 0; a < 4; a++) {
            const __nv_bfloat16* src = (a & 1) ? g_qkvl : g_qkvh;
            const int col = (a < 2) ? colK : colV;
            __nv_bfloat16* dst = sKV[w][a];
#pragma unroll
            for (int i = lane; i < 256; i += 32) {
                int row = i >> 1, half = i & 1;
                *(uint4*)&dst[row * kAStr + half * 8] =
                    *(const uint4*)&src[(size_t)(bn * 128 + row) * 384 + col + half * 8];
            }
        }
    }
    __syncwarp();

    uint32_t kvb[4];
#pragma unroll
    for (int a = 0; a < 4; a++)
        kvb[a] = (uint32_t)__cvta_generic_to_shared(&sKV[w][a][0]);

    const uint32_t offK = (uint32_t)((lane & 7) * 48 + ((lane >> 3) & 1) * 16);
    const uint32_t offV = (uint32_t)(((lane & 7) + ((lane >> 3) & 1) * 8) * 48);

    for (int mt = 0; mt < 8; mt++) {
        const size_t r0 = (size_t)(bn * 128 + mt * 16 + g) * 384 + h * 16 + tig * 2;
        const size_t r1 = r0 + 8 * 384;
        uint32_t qh[4], ql[4];
        qh[0] = *(const uint32_t*)&g_qkvh[r0];
        qh[1] = *(const uint32_t*)&g_qkvh[r1];
        qh[2] = *(const uint32_t*)&g_qkvh[r0 + 8];
        qh[3] = *(const uint32_t*)&g_qkvh[r1 + 8];
        ql[0] = *(const uint32_t*)&g_qkvl[r0];
        ql[1] = *(const uint32_t*)&g_qkvl[r1];
        ql[2] = *(const uint32_t*)&g_qkvl[r0 + 8];
        ql[3] = *(const uint32_t*)&g_qkvl[r1 + 8];

        float c[16][4];
#pragma unroll
        for (int j = 0; j < 16; j++)
#pragma unroll
            for (int t = 0; t < 4; t++) c[j][t] = 0.f;

#pragma unroll
        for (int j = 0; j < 16; j++) {
            uint32_t kh[2], kl[2];
            LDSM2(kh, kvb[0] + j * 384 + offK);
            LDSM2(kl, kvb[1] + j * 384 + offK);
            mma16816(c[j], qh, kh);
            mma16816(c[j], qh, kl);
            mma16816(c[j], ql, kh);
        }

        float mx0 = -1e30f, mx1 = -1e30f;
#pragma unroll
        for (int j = 0; j < 16; j++) {
            c[j][0] *= 0.25f; c[j][1] *= 0.25f;
            c[j][2] *= 0.25f; c[j][3] *= 0.25f;
            mx0 = fmaxf(mx0, fmaxf(c[j][0], c[j][1]));
            mx1 = fmaxf(mx1, fmaxf(c[j][2], c[j][3]));
        }
        mx0 = fmaxf(mx0, __shfl_xor_sync(~0u, mx0, 1));
        mx0 = fmaxf(mx0, __shfl_xor_sync(~0u, mx0, 2));
        mx1 = fmaxf(mx1, __shfl_xor_sync(~0u, mx1, 1));
        mx1 = fmaxf(mx1, __shfl_xor_sync(~0u, mx1, 2));
        float sm0 = 0.f, sm1 = 0.f;
#pragma unroll
        for (int j = 0; j < 16; j++) {
            c[j][0] = __expf(c[j][0] - mx0); sm0 += c[j][0];
            c[j][1] = __expf(c[j][1] - mx0); sm0 += c[j][1];
            c[j][2] = __expf(c[j][2] - mx1); sm1 += c[j][2];
            c[j][3] = __expf(c[j][3] - mx1); sm1 += c[j][3];
        }
        sm0 += __shfl_xor_sync(~0u, sm0, 1);
        sm0 += __shfl_xor_sync(~0u, sm0, 2);
        sm1 += __shfl_xor_sync(~0u, sm1, 1);
        sm1 += __shfl_xor_sync(~0u, sm1, 2);

        float o[2][4];
#pragma unroll
        for (int n = 0; n < 2; n++)
#pragma unroll
            for (int t = 0; t < 4; t++) o[n][t] = 0.f;

#pragma unroll
        for (int ks = 0; ks < 8; ks++) {
            uint32_t ph[4], pl[4];
#pragma unroll
            for (int half = 0; half < 2; half++) {
                const float* cv = c[2 * ks + half];
                __nv_bfloat162 h01, l01, h23, l23;
                split2(cv[0], h01.x, l01.x); split2(cv[1], h01.y, l01.y);
                split2(cv[2], h23.x, l23.x); split2(cv[3], h23.y, l23.y);
                ph[half * 2 + 0] = *(uint32_t*)&h01;
                ph[half * 2 + 1] = *(uint32_t*)&h23;
                pl[half * 2 + 0] = *(uint32_t*)&l01;
                pl[half * 2 + 1] = *(uint32_t*)&l23;
            }
            uint32_t pha[4] = {ph[0], ph[1], ph[2], ph[3]};
            uint32_t pla[4] = {pl[0], pl[1], pl[2], pl[3]};
#pragma unroll
            for (int n = 0; n < 2; n++) {
                uint32_t vh[2], vl[2];
                LDSM2T(vh, kvb[2] + ks * 768 + offV + n * 16);
                LDSM2T(vl, kvb[3] + ks * 768 + offV + n * 16);
                mma16816(o[n], pha, vh);
                mma16816(o[n], pha, vl);
                mma16816(o[n], pla, vh);
            }
        }

        const float i0 = 1.f / sm0, i1 = 1.f / sm1;
        const size_t ro = (size_t)(bn * 128 + mt * 16 + g) * 128 + h * 16;
#pragma unroll
        for (int n = 0; n < 2; n++) {
            const size_t cA = ro + n * 8 + tig * 2;
            const size_t cB = cA + 8 * 128;
            __nv_bfloat162 h0, l0, h1, l1;
            split2(o[n][0] * i0, h0.x, l0.x);
            split2(o[n][1] * i0, h0.y, l0.y);
            split2(o[n][2] * i1, h1.x, l1.x);
            split2(o[n][3] * i1, h1.y, l1.y);
            *(__nv_bfloat162*)&g_aoh[cA] = h0;
            *(__nv_bfloat162*)&g_aol[cA] = l0;
            *(__nv_bfloat162*)&g_aoh[cB] = h1;
            *(__nv_bfloat162*)&g_aol[cB] = l1;
        }
    }
}

// ---------------- node score: warp per row ---------------------------------
__global__ __launch_bounds__(256) void s_kernel() {
    const int wid = threadIdx.x >> 5, lane = threadIdx.x & 31;
    const int row = blockIdx.x * 8 + wid;
    const float4 e4 = *(const float4*)&g_e[(size_t)row * kD + lane * 4];
    const float4 x4 = *(const float4*)&g_x[(size_t)row * kD + lane * 4];
    float p = e4.x * x4.x + e4.y * x4.y + e4.z * x4.z + e4.w * x4.w;
#pragma unroll
    for (int o = 16; o > 0; o >>= 1) p += __shfl_xor_sync(~0u, p, o);
    if (lane == 0) {
        int b = row >> 13;
        int rem = row & 8191;
        int n = rem >> 7, tt = rem & 127;
        g_s[b * kNN + tt * kNA + n] = p;
    }
}

// ---------------- edge segment-sum ----------------------------------------
__global__ void edge_kernel(const int* __restrict__ ei,
                            const float* __restrict__ ew) {
    int idx = blockIdx.x * blockDim.x + threadIdx.x;
    if (idx >= kB * kE) return;
    int b = idx / kE, e = idx - b * kE;
    int src = ei[b * 2 * kE + e];
    int dst = ei[b * 2 * kE + kE + e];
    atomicAdd(&g_gout[b * kNN + dst], ew[idx] * g_s[b * kNN + src]);
}

// ---------------- global mean/var over gout -------------------------------
__global__ __launch_bounds__(256) void stats_kernel() {
    int i = blockIdx.x * blockDim.x + threadIdx.x;
    double s = 0.0, s2 = 0.0;
    for (int k = i; k < kB * kNN; k += gridDim.x * blockDim.x) {
        double v = (double)g_gout[k];
        s += v; s2 += v * v;
    }
#pragma unroll
    for (int o = 16; o > 0; o >>= 1) {
        s  += __shfl_xor_sync(~0u, s, o);
        s2 += __shfl_xor_sync(~0u, s2, o);
    }
    __shared__ double ws[8][2];
    int w = threadIdx.x >> 5;
    if ((threadIdx.x & 31) == 0) { ws[w][0] = s; ws[w][1] = s2; }
    __syncthreads();
    if (threadIdx.x == 0) {
        double a = 0, b2 = 0;
        for (int k = 0; k < 8; k++) { a += ws[k][0]; b2 += ws[k][1]; }
        atomicAdd(&g_red[0], a);
        atomicAdd(&g_red[1], b2);
    }
}

// ---------------- batchnorm + rank-1 output --------------------------------
__global__ void out_kernel(const float* __restrict__ bng,
                           const float* __restrict__ bnb,
                           const float* __restrict__ lw,
                           const float* __restrict__ lb,
                           float* __restrict__ out) {
    int idx = blockIdx.x * blockDim.x + threadIdx.x;
    if (idx >= kRows * kD) return;
    int d = idx & 127;
    int t = (idx >> 7) & 127;
    int n = (idx >> 14) & 63;
    int b = idx >> 20;
    const double inv_n = 1.0 / (double)(kB * kNN);
    double m = g_red[0] * inv_n;
    double var = g_red[1] * inv_n - m * m;
    double rs = 1.0 / sqrt(var + 1e-5);
    float gv = g_gout[b * kNN + t * kNA + n];
    float norm = (float)(((double)gv - m) * rs) * bng[0] + bnb[0];
    out[idx] = norm * lw[d] + lb[d];
}

// ---------------- launch ---------------------------------------------------
extern "C" void kernel_launch(void* const* d_in, const int* in_sizes, int n_in,
                              void* d_out, int out_size) {
    const float* feat  = (const float*)d_in[0];
    const int*   eidx  = (const int*)d_in[1];
    const float* ew    = (const float*)d_in[2];
    const float* histw = (const float*)d_in[3];
    const float* histb = (const float*)d_in[4];
    const float* wq    = (const float*)d_in[5];
    const float* bq    = (const float*)d_in[6];
    const float* wk    = (const float*)d_in[7];
    const float* bk    = (const float*)d_in[8];
    const float* wv    = (const float*)d_in[9];
    const float* bv    = (const float*)d_in[10];
    const float* wo    = (const float*)d_in[11];
    const float* bo    = (const float*)d_in[12];
    const float* ln1g  = (const float*)d_in[13];
    const float* ln1b  = (const float*)d_in[14];
    const float* fw1   = (const float*)d_in[15];
    const float* fb1   = (const float*)d_in[16];
    const float* fw2   = (const float*)d_in[17];
    const float* fb2   = (const float*)d_in[18];
    const float* ln2g  = (const float*)d_in[19];
    const float* ln2b  = (const float*)d_in[20];
    const float* bng   = (const float*)d_in[21];
    const float* bnb   = (const float*)d_in[22];
    const float* lgw   = (const float*)d_in[23];
    const float* lgb   = (const float*)d_in[24];
    float* out = (float*)d_out;

    float *pe, *ph1, *pbqkv;
    __nv_bfloat16 *pwh, *pwl, *peh, *pel, *paoh, *paol, *ph1h, *ph1l, *pffh, *pffl,
                  *pqkvh, *pqkvl;
    cudaGetSymbolAddress((void**)&pe,   g_e);
    cudaGetSymbolAddress((void**)&ph1,  g_h1);
    cudaGetSymbolAddress((void**)&pwh,  g_wth);
    cudaGetSymbolAddress((void**)&pwl,  g_wtl);
    cudaGetSymbolAddress((void**)&pbqkv, g_bqkv);
    cudaGetSymbolAddress((void**)&peh,  g_eh);
    cudaGetSymbolAddress((void**)&pel,  g_el);
    cudaGetSymbolAddress((void**)&paoh, g_aoh);
    cudaGetSymbolAddress((void**)&paol, g_aol);
    cudaGetSymbolAddress((void**)&ph1h, g_h1h);
    cudaGetSymbolAddress((void**)&ph1l, g_h1l);
    cudaGetSymbolAddress((void**)&pffh, g_ffh);
    cudaGetSymbolAddress((void**)&pffl, g_ffl);
    cudaGetSymbolAddress((void**)&pqkvh, g_qkvh);
    cudaGetSymbolAddress((void**)&pqkvl, g_qkvl);

    cudaFuncSetAttribute(gemm_mma<0>,
                         cudaFuncAttributeMaxDynamicSharedMemorySize, kGemmSmem);
    cudaFuncSetAttribute(gemm_mma<1>,
                         cudaFuncAttributeMaxDynamicSharedMemorySize, kGemmSmem);
    cudaFuncSetAttribute(gemm_mma<2>,
                         cudaFuncAttributeMaxDynamicSharedMemorySize, kGemmSmem);
    cudaFuncSetAttribute(gemm_mma<3>,
                         cudaFuncAttributeMaxDynamicSharedMemorySize, kGemmSmem);

    // launch order matters for ncu (-s 5 -c 1 profiles launch #6 = O-proj GEMM)
    setup_kernel<<<(kB * kNN + 255) / 256, 256>>>(bq, bk, bv);
    wconv_all<<<(kL * kWL + 255) / 256, 256>>>(wq, wk, wv, wo, fw1, fw2);
    hist_pe_kernel<<<kRows * kD / 256, 256>>>(feat, histw, histb);

    const int MT = kRows / 128;  // 256 M tiles
    for (int l = 0; l < kL; l++) {
        const int base = l * kWL;
        // QKV fused: N=384, K=128 -> bf16 splits
        gemm_mma<3><<<dim3(3, MT), 256, kGemmSmem>>>(
            peh, pel, pwh + base, pwl + base, pbqkv + l * 384,
            nullptr, pqkvh, pqkvl, nullptr, nullptr, nullptr, 384, 128);
        attn_mma_kernel<<<dim3(kB * kNA, kH / 2), 64>>>();
        // O proj + residual(e) + LN1 -> h1 (f32 + splits)
        gemm_mma<2><<<dim3(1, MT), 256, kGemmSmem>>>(
            paoh, paol, pwh + base + 49152, pwl + base + 49152, bo + l * kD,
            ph1, ph1h, ph1l, pe, ln1g + l * kD, ln1b + l * kD, 128, 128);
        // FF1: N=512, K=128, relu + split out
        gemm_mma<1><<<dim3(4, MT), 256, kGemmSmem>>>(
            ph1h, ph1l, pwh + base + 65536, pwl + base + 65536, fb1 + l * kDFF,
            nullptr, pffh, pffl, nullptr, nullptr, nullptr, 512, 128);
        // FF2 + residual(h1) + LN2 -> e (f32 + splits)
        gemm_mma<2><<<dim3(1, MT), 256, kGemmSmem>>>(
            pffh, pffl, pwh + base + 131072, pwl + base + 131072, fb2 + l * kD,
            pe, peh, pel, ph1, ln2g + l * kD, ln2b + l * kD, 128, 512);
    }

    s_kernel<<<kRows / 8, 256>>>();
    edge_kernel<<<(kB * kE + 255) / 256, 256>>>(eidx, ew);
    stats_kernel<<<64, 256>>>();
    out_kernel<<<(kRows * kD + 255) / 256, 256>>>(bng, bnb, lgw, lgb, out);
}